// round 1
// baseline (speedup 1.0000x reference)
#include <cuda_runtime.h>

#define NN 100000
#define NE 1000000
#define NG 512
#define HID 64
#define EDIM 32
#define ZW 160
#define NLAYERS 4

typedef unsigned long long ull;

// ---------------- scratch (static device globals; no allocation) ----------------
__device__ float d_x[NN * HID];      // node features
__device__ float d_Af[NN * HID];     // x @ Wf[0:64]  + bf   (dst / x_i part)
__device__ float d_Bf[NN * HID];     // x @ Wf[64:128]       (src / x_j part)
__device__ float d_As[NN * HID];     // x @ Ws[0:64]  + bs
__device__ float d_Bs[NN * HID];     // x @ Ws[64:128]
__device__ float d_agg[NN * HID];    // edge aggregation, then x_new in-place
__device__ double d_sum1[HID];       // cbn sums
__device__ double d_sumsq1[HID];
__device__ double d_sum2[HID];       // obn sums
__device__ double d_sumsq2[HID];
__device__ float d_pool[NG * HID];
__device__ float d_cnt[NG];

// ---------------- packed f32x2 helpers (Blackwell) ----------------
__device__ __forceinline__ ull pk2(float a, float b) {
    ull r; asm("mov.b64 %0,{%1,%2};" : "=l"(r) : "f"(a), "f"(b)); return r;
}
__device__ __forceinline__ void upk2(ull v, float& a, float& b) {
    asm("mov.b64 {%0,%1},%2;" : "=f"(a), "=f"(b) : "l"(v));
}
__device__ __forceinline__ ull ffma2(ull a, ull b, ull c) {
    ull d; asm("fma.rn.f32x2 %0,%1,%2,%3;" : "=l"(d) : "l"(a), "l"(b), "l"(c)); return d;
}

__device__ __forceinline__ float sigmoidf_(float x) {
    return __fdividef(1.0f, 1.0f + __expf(-x));
}
__device__ __forceinline__ float softplusf_(float x) {
    // log1p(exp(-|x|)) + max(x, 0), fast-math variant; abs error negligible at 1e-3 tol
    float e = __expf(-fabsf(x));
    return fmaxf(x, 0.0f) + __logf(1.0f + e);
}

// ---------------- kernels ----------------

__global__ void k_gather(const int* __restrict__ z, const float* __restrict__ emb) {
    int i = blockIdx.x * blockDim.x + threadIdx.x;
    if (i < NN * HID) {
        int n = i >> 6, c = i & 63;
        d_x[i] = emb[z[n] * HID + c];
    }
}

// Per-node pre-GEMM: 4 warps per block, warp m computes matrix m over a 64-node tile.
// Each lane holds its two output channels of W (64 k-values) in registers.
__global__ __launch_bounds__(128) void k_node_pre(
    const float* __restrict__ Wf, const float* __restrict__ bf,
    const float* __restrict__ Ws, const float* __restrict__ bs)
{
    __shared__ float sx[64][HID];
    int warp = threadIdx.x >> 5;   // 0..3 = which output matrix
    int lane = threadIdx.x & 31;

    const float* Wsrc;
    float bias0 = 0.f, bias1 = 0.f;
    float* outp;
    if (warp == 0)      { Wsrc = Wf;            bias0 = bf[2*lane]; bias1 = bf[2*lane+1]; outp = d_Af; }
    else if (warp == 1) { Wsrc = Wf + 64 * HID;                                            outp = d_Bf; }
    else if (warp == 2) { Wsrc = Ws;            bias0 = bs[2*lane]; bias1 = bs[2*lane+1]; outp = d_As; }
    else                { Wsrc = Ws + 64 * HID;                                            outp = d_Bs; }

    ull w[64];
#pragma unroll
    for (int k = 0; k < 64; k++) {
        float2 t = *(const float2*)(Wsrc + k * HID + 2 * lane);
        w[k] = pk2(t.x, t.y);
    }

    int nb = blockIdx.x * 64;
    int nmax = NN - nb; if (nmax > 64) nmax = 64;

    for (int i = threadIdx.x; i < nmax * HID; i += 128)
        sx[i >> 6][i & 63] = d_x[nb * HID + i];
    __syncthreads();

    for (int n = 0; n < nmax; n++) {
        ull a0 = pk2(bias0, bias1), a1 = 0ull, a2 = 0ull, a3 = 0ull;
#pragma unroll
        for (int k = 0; k < 64; k += 4) {
            float x0 = sx[n][k], x1 = sx[n][k+1], x2 = sx[n][k+2], x3 = sx[n][k+3];
            a0 = ffma2(pk2(x0, x0), w[k],   a0);
            a1 = ffma2(pk2(x1, x1), w[k+1], a1);
            a2 = ffma2(pk2(x2, x2), w[k+2], a2);
            a3 = ffma2(pk2(x3, x3), w[k+3], a3);
        }
        float r0a, r0b, r1a, r1b, r2a, r2b, r3a, r3b;
        upk2(a0, r0a, r0b); upk2(a1, r1a, r1b); upk2(a2, r2a, r2b); upk2(a3, r3a, r3b);
        float2 r; r.x = (r0a + r1a) + (r2a + r3a); r.y = (r0b + r1b) + (r2b + r3b);
        *(float2*)(outp + (nb + n) * HID + 2 * lane) = r;
    }
}

__global__ void k_zero_layer() {
    int i = blockIdx.x * blockDim.x + threadIdx.x;
    if (i < NN * HID) d_agg[i] = 0.f;
    if (blockIdx.x == 0 && threadIdx.x < 64) {
        d_sum1[threadIdx.x] = 0.0; d_sumsq1[threadIdx.x] = 0.0;
        d_sum2[threadIdx.x] = 0.0; d_sumsq2[threadIdx.x] = 0.0;
    }
}

__global__ void k_zero_pool() {
    int i = blockIdx.x * blockDim.x + threadIdx.x;
    if (i < NG * HID) d_pool[i] = 0.f;
    if (i < NG) d_cnt[i] = 0.f;
}

// Edge kernel: one warp per edge, W_edge (32x64, f and s) resident in registers.
__global__ __launch_bounds__(128) void k_edge(
    const int* __restrict__ ei, const float* __restrict__ ea,
    const float* __restrict__ Wf, const float* __restrict__ Ws)
{
    int lane = threadIdx.x & 31;
    int gw = (blockIdx.x * blockDim.x + threadIdx.x) >> 5;
    int nw = (gridDim.x * blockDim.x) >> 5;

    ull wf[32], ws[32];
#pragma unroll
    for (int k = 0; k < 32; k++) {
        float2 a = *(const float2*)(Wf + (128 + k) * HID + 2 * lane);
        float2 b = *(const float2*)(Ws + (128 + k) * HID + 2 * lane);
        wf[k] = pk2(a.x, a.y);
        ws[k] = pk2(b.x, b.y);
    }

    for (int e = gw; e < NE; e += nw) {
        int src = ei[e];
        int dst = ei[NE + e];
        float eav = ea[e * EDIM + lane];

        float2 af  = *(const float2*)(d_Af + dst * HID + 2 * lane);
        float2 bfv = *(const float2*)(d_Bf + src * HID + 2 * lane);
        float2 as  = *(const float2*)(d_As + dst * HID + 2 * lane);
        float2 bsv = *(const float2*)(d_Bs + src * HID + 2 * lane);

        ull accf0 = 0ull, accf1 = 0ull, accs0 = 0ull, accs1 = 0ull;
#pragma unroll
        for (int k = 0; k < 32; k += 2) {
            float e0 = __shfl_sync(0xffffffffu, eav, k);
            float e1 = __shfl_sync(0xffffffffu, eav, k + 1);
            ull p0 = pk2(e0, e0), p1 = pk2(e1, e1);
            accf0 = ffma2(p0, wf[k],     accf0);
            accf1 = ffma2(p1, wf[k + 1], accf1);
            accs0 = ffma2(p0, ws[k],     accs0);
            accs1 = ffma2(p1, ws[k + 1], accs1);
        }
        float f0a, f0b, f1a, f1b, s0a, s0b, s1a, s1b;
        upk2(accf0, f0a, f0b); upk2(accf1, f1a, f1b);
        upk2(accs0, s0a, s0b); upk2(accs1, s1a, s1b);

        float pf0 = (f0a + f1a) + (af.x + bfv.x);
        float pf1 = (f0b + f1b) + (af.y + bfv.y);
        float ps0 = (s0a + s1a) + (as.x + bsv.x);
        float ps1 = (s0b + s1b) + (as.y + bsv.y);

        float m0 = sigmoidf_(pf0) * softplusf_(ps0);
        float m1 = sigmoidf_(pf1) * softplusf_(ps1);

        float* dp = d_agg + dst * HID + 2 * lane;
        asm volatile("red.global.add.v2.f32 [%0], {%1,%2};"
                     :: "l"(dp), "f"(m0), "f"(m1) : "memory");
    }
}

// channel-wise sum / sumsq of d_agg -> d_sum1 / d_sumsq1  (double precision)
__global__ void k_stats_agg() {
    int tid = threadIdx.x;
    int c = tid & 63;
    double s = 0.0, q = 0.0;
    int stride = gridDim.x * blockDim.x;  // multiple of 64 -> c invariant
    for (int i = blockIdx.x * blockDim.x + tid; i < NN * HID; i += stride) {
        float v = d_agg[i];
        s += v; q += (double)v * v;
    }
    __shared__ double ss[256], sq[256];
    ss[tid] = s; sq[tid] = q;
    __syncthreads();
    if (tid < 64) {
        s = ss[tid] + ss[tid + 64] + ss[tid + 128] + ss[tid + 192];
        q = sq[tid] + sq[tid + 64] + sq[tid + 128] + sq[tid + 192];
        atomicAdd(&d_sum1[c], s);
        atomicAdd(&d_sumsq1[c], q);
    }
}

// apply cbn + residual, write x_new into d_agg, accumulate obn stats
__global__ void k_apply_cbn(const float* __restrict__ gc, const float* __restrict__ bc) {
    int tid = threadIdx.x;
    int c = tid & 63;
    double mean = d_sum1[c] * (1.0 / NN);
    double var  = d_sumsq1[c] * (1.0 / NN) - mean * mean;
    float rs = (float)rsqrt(var + 1e-5);
    float mn = (float)mean;
    float g = gc[c], b = bc[c];

    double s = 0.0, q = 0.0;
    int stride = gridDim.x * blockDim.x;
    for (int i = blockIdx.x * blockDim.x + tid; i < NN * HID; i += stride) {
        float xn = (d_agg[i] - mn) * rs * g + b + d_x[i];
        d_agg[i] = xn;
        s += xn; q += (double)xn * xn;
    }
    __shared__ double ss[256], sq[256];
    ss[tid] = s; sq[tid] = q;
    __syncthreads();
    if (tid < 64) {
        s = ss[tid] + ss[tid + 64] + ss[tid + 128] + ss[tid + 192];
        q = sq[tid] + sq[tid + 64] + sq[tid + 128] + sq[tid + 192];
        atomicAdd(&d_sum2[c], s);
        atomicAdd(&d_sumsq2[c], q);
    }
}

// apply obn + softplus -> d_x
__global__ void k_apply_obn(const float* __restrict__ go, const float* __restrict__ bo) {
    int i = blockIdx.x * blockDim.x + threadIdx.x;
    if (i >= NN * HID) return;
    int c = i & 63;
    double mean = d_sum2[c] * (1.0 / NN);
    double var  = d_sumsq2[c] * (1.0 / NN) - mean * mean;
    float rs = (float)rsqrt(var + 1e-5);
    float xv = (d_agg[i] - (float)mean) * rs * go[c] + bo[c];
    d_x[i] = softplusf_(xv);
}

__global__ void k_pool(const int* __restrict__ batch) {
    int i = blockIdx.x * blockDim.x + threadIdx.x;
    if (i < NN * 16) {
        int n = i >> 4, q = i & 15;
        int g = batch[n];
        float4 v = *(const float4*)(d_x + n * HID + 4 * q);
        float* p = d_pool + g * HID + 4 * q;
        asm volatile("red.global.add.v4.f32 [%0], {%1,%2,%3,%4};"
                     :: "l"(p), "f"(v.x), "f"(v.y), "f"(v.z), "f"(v.w) : "memory");
    }
}

__global__ void k_cnt(const int* __restrict__ batch) {
    int n = blockIdx.x * blockDim.x + threadIdx.x;
    if (n < NN) atomicAdd(&d_cnt[batch[n]], 1.0f);
}

__global__ void k_head(const float* __restrict__ W1, const float* __restrict__ b1,
                       const float* __restrict__ W2, const float* __restrict__ b2,
                       float* __restrict__ out)
{
    int g = blockIdx.x;
    int t = threadIdx.x;  // 0..63
    __shared__ float sp[64];
    __shared__ float sh[64];
    float cnt = fmaxf(d_cnt[g], 1.0f);
    sp[t] = d_pool[g * HID + t] / cnt;
    __syncthreads();
    float acc = b1[t];
#pragma unroll
    for (int k = 0; k < 64; k++)
        acc = fmaf(sp[k], W1[k * HID + t], acc);
    float h = acc * sigmoidf_(acc);   // silu
    sh[t] = h * W2[t];
    __syncthreads();
    if (t < 32) {
        float v = sh[t] + sh[t + 32];
#pragma unroll
        for (int o = 16; o > 0; o >>= 1)
            v += __shfl_down_sync(0xffffffffu, v, o);
        if (t == 0) out[g] = v + b2[0];
    }
}

// ---------------- launch ----------------
extern "C" void kernel_launch(void* const* d_in, const int* in_sizes, int n_in,
                              void* d_out, int out_size) {
    const int*   z     = (const int*)  d_in[0];
    const int*   ei    = (const int*)  d_in[1];
    const float* ea    = (const float*)d_in[2];
    const int*   batch = (const int*)  d_in[3];
    const float* emb   = (const float*)d_in[4];
    const float* Wf    = (const float*)d_in[5];
    const float* bf    = (const float*)d_in[6];
    const float* Ws    = (const float*)d_in[7];
    const float* bs    = (const float*)d_in[8];
    const float* gc    = (const float*)d_in[9];
    const float* bc    = (const float*)d_in[10];
    const float* go    = (const float*)d_in[11];
    const float* bo    = (const float*)d_in[12];
    const float* W1    = (const float*)d_in[13];
    const float* b1    = (const float*)d_in[14];
    const float* W2    = (const float*)d_in[15];
    const float* b2    = (const float*)d_in[16];
    float* out = (float*)d_out;

    k_gather<<<(NN * HID + 255) / 256, 256>>>(z, emb);

    for (int l = 0; l < NLAYERS; l++) {
        const float* Wfl = Wf + l * ZW * HID;
        const float* Wsl = Ws + l * ZW * HID;
        k_node_pre<<<(NN + 63) / 64, 128>>>(Wfl, bf + l * HID, Wsl, bs + l * HID);
        k_zero_layer<<<(NN * HID + 255) / 256, 256>>>();
        k_edge<<<2368, 128>>>(ei, ea, Wfl, Wsl);
        k_stats_agg<<<256, 256>>>();
        k_apply_cbn<<<256, 256>>>(gc + l * HID, bc + l * HID);
        k_apply_obn<<<(NN * HID + 255) / 256, 256>>>(go + l * HID, bo + l * HID);
    }

    k_zero_pool<<<(NG * HID + 255) / 256, 256>>>();
    k_pool<<<(NN * 16 + 255) / 256, 256>>>(batch);
    k_cnt<<<(NN + 255) / 256, 256>>>(batch);
    k_head<<<NG, 64>>>(W1, b1, W2, b2, out);
}

// round 2
// speedup vs baseline: 1.4583x; 1.4583x over previous
#include <cuda_runtime.h>
#include <cuda_fp16.h>

#define NN 100000
#define NE 1000000
#define NG 512
#define HID 64
#define EDIM 32
#define ZW 160
#define NLAYERS 4

typedef unsigned long long ull;

// ---------------- scratch (static device globals; no allocation) ----------------
__device__ float d_x[NN * HID];      // node features
__device__ float d_Af[NN * HID];     // x @ Wf[0:64]  + bf   (dst / x_i part)
__device__ float d_Bf[NN * HID];     // x @ Wf[64:128]       (src / x_j part)
__device__ float d_As[NN * HID];     // x @ Ws[0:64]  + bs
__device__ float d_Bs[NN * HID];     // x @ Ws[64:128]
__device__ float d_agg[NN * HID];    // edge aggregation, then x_new in-place
__device__ __half d_E[NE * 128];     // per-edge pre-acts: [e][0:64]=f, [64:128]=s
__device__ double d_sum1[HID];       // cbn sums
__device__ double d_sumsq1[HID];
__device__ double d_sum2[HID];       // obn sums
__device__ double d_sumsq2[HID];
__device__ float d_pool[NG * HID];
__device__ float d_cnt[NG];

// ---------------- packed f32x2 helpers (Blackwell) ----------------
__device__ __forceinline__ ull pk2(float a, float b) {
    ull r; asm("mov.b64 %0,{%1,%2};" : "=l"(r) : "f"(a), "f"(b)); return r;
}
__device__ __forceinline__ void upk2(ull v, float& a, float& b) {
    asm("mov.b64 {%0,%1},%2;" : "=f"(a), "=f"(b) : "l"(v));
}
__device__ __forceinline__ ull ffma2(ull a, ull b, ull c) {
    ull d; asm("fma.rn.f32x2 %0,%1,%2,%3;" : "=l"(d) : "l"(a), "l"(b), "l"(c)); return d;
}

__device__ __forceinline__ float sigmoidf_(float x) {
    return __fdividef(1.0f, 1.0f + __expf(-x));
}
__device__ __forceinline__ float softplusf_(float x) {
    float e = __expf(-fabsf(x));
    return fmaxf(x, 0.0f) + __logf(1.0f + e);
}

// ---------------- kernels ----------------

__global__ void k_gather(const int* __restrict__ z, const float* __restrict__ emb) {
    int i = blockIdx.x * blockDim.x + threadIdx.x;
    if (i < NN * HID) {
        int n = i >> 6, c = i & 63;
        d_x[i] = emb[z[n] * HID + c];
    }
}

// Per-node pre-GEMM: 4 warps per block, warp m computes matrix m over a 64-node tile.
__global__ __launch_bounds__(128) void k_node_pre(
    const float* __restrict__ Wf, const float* __restrict__ bf,
    const float* __restrict__ Ws, const float* __restrict__ bs)
{
    __shared__ float sx[64][HID];
    int warp = threadIdx.x >> 5;
    int lane = threadIdx.x & 31;

    const float* Wsrc;
    float bias0 = 0.f, bias1 = 0.f;
    float* outp;
    if (warp == 0)      { Wsrc = Wf;            bias0 = bf[2*lane]; bias1 = bf[2*lane+1]; outp = d_Af; }
    else if (warp == 1) { Wsrc = Wf + 64 * HID;                                            outp = d_Bf; }
    else if (warp == 2) { Wsrc = Ws;            bias0 = bs[2*lane]; bias1 = bs[2*lane+1]; outp = d_As; }
    else                { Wsrc = Ws + 64 * HID;                                            outp = d_Bs; }

    ull w[64];
#pragma unroll
    for (int k = 0; k < 64; k++) {
        float2 t = *(const float2*)(Wsrc + k * HID + 2 * lane);
        w[k] = pk2(t.x, t.y);
    }

    int nb = blockIdx.x * 64;
    int nmax = NN - nb; if (nmax > 64) nmax = 64;

    for (int i = threadIdx.x; i < nmax * HID; i += 128)
        sx[i >> 6][i & 63] = d_x[nb * HID + i];
    __syncthreads();

    for (int n = 0; n < nmax; n++) {
        ull a0 = pk2(bias0, bias1), a1 = 0ull, a2 = 0ull, a3 = 0ull;
#pragma unroll
        for (int k = 0; k < 64; k += 4) {
            float x0 = sx[n][k], x1 = sx[n][k+1], x2 = sx[n][k+2], x3 = sx[n][k+3];
            a0 = ffma2(pk2(x0, x0), w[k],   a0);
            a1 = ffma2(pk2(x1, x1), w[k+1], a1);
            a2 = ffma2(pk2(x2, x2), w[k+2], a2);
            a3 = ffma2(pk2(x3, x3), w[k+3], a3);
        }
        float r0a, r0b, r1a, r1b, r2a, r2b, r3a, r3b;
        upk2(a0, r0a, r0b); upk2(a1, r1a, r1b); upk2(a2, r2a, r2b); upk2(a3, r3a, r3b);
        float2 r; r.x = (r0a + r1a) + (r2a + r3a); r.y = (r0b + r1b) + (r2b + r3b);
        *(float2*)(outp + (nb + n) * HID + 2 * lane) = r;
    }
}

__global__ void k_zero_layer() {
    int i = blockIdx.x * blockDim.x + threadIdx.x;
    if (i < NN * HID) d_agg[i] = 0.f;
    if (blockIdx.x == 0 && threadIdx.x < 64) {
        d_sum1[threadIdx.x] = 0.0; d_sumsq1[threadIdx.x] = 0.0;
        d_sum2[threadIdx.x] = 0.0; d_sumsq2[threadIdx.x] = 0.0;
    }
}

__global__ void k_zero_pool() {
    int i = blockIdx.x * blockDim.x + threadIdx.x;
    if (i < NG * HID) d_pool[i] = 0.f;
    if (i < NG) d_cnt[i] = 0.f;
}

// Edge GEMM: E[e, 0:128] = ea[e, 0:32] @ [Wf_edge | Ws_edge], stored fp16.
// Block = 128 threads; tile = 32 edges; warp (w&1) picks f/s matrix,
// warp (w>>1) picks edge half-tile. Weights live in 32 ull regs per lane.
__global__ __launch_bounds__(128) void k_edge_gemm(
    const float* __restrict__ ea,
    const float* __restrict__ Wf, const float* __restrict__ Ws)
{
    __shared__ float sea[32][EDIM];
    int warp = threadIdx.x >> 5;
    int lane = threadIdx.x & 31;
    const float* W = (warp & 1) ? Ws : Wf;

    ull w[32];
#pragma unroll
    for (int k = 0; k < 32; k++) {
        float2 t = *(const float2*)(W + (128 + k) * HID + 2 * lane);
        w[k] = pk2(t.x, t.y);
    }

    int eoff = (warp >> 1) * 16;
    int outc = (warp & 1) * 64 + 2 * lane;

    for (int base = blockIdx.x * 32; base < NE; base += gridDim.x * 32) {
        // cooperative load of ea tile (32 edges x 32 floats), streaming
        const float4* s4 = (const float4*)(ea + base * EDIM);
        float4* t4 = (float4*)&sea[0][0];
#pragma unroll
        for (int i = threadIdx.x; i < 256; i += 128)
            t4[i] = __ldcs(s4 + i);
        __syncthreads();

#pragma unroll 2
        for (int t = 0; t < 16; t++) {
            int e = eoff + t;
            ull a0 = 0ull, a1 = 0ull, a2 = 0ull, a3 = 0ull;
#pragma unroll
            for (int k = 0; k < 32; k += 4) {
                float4 v = *(const float4*)&sea[e][k];
                a0 = ffma2(pk2(v.x, v.x), w[k],   a0);
                a1 = ffma2(pk2(v.y, v.y), w[k+1], a1);
                a2 = ffma2(pk2(v.z, v.z), w[k+2], a2);
                a3 = ffma2(pk2(v.w, v.w), w[k+3], a3);
            }
            float r0a, r0b, r1a, r1b, r2a, r2b, r3a, r3b;
            upk2(a0, r0a, r0b); upk2(a1, r1a, r1b);
            upk2(a2, r2a, r2b); upk2(a3, r3a, r3b);
            float c0 = (r0a + r1a) + (r2a + r3a);
            float c1 = (r0b + r1b) + (r2b + r3b);
            __half2 h = __floats2half2_rn(c0, c1);
            __stcs((__half2*)(d_E + (ull)(base + e) * 128 + outc), h);
        }
        __syncthreads();
    }
}

// Edge apply: one warp per edge. Gather node terms, add E, activate, scatter.
__global__ __launch_bounds__(256) void k_edge_apply(const int* __restrict__ ei) {
    int lane = threadIdx.x & 31;
    int e = (blockIdx.x * blockDim.x + threadIdx.x) >> 5;
    if (e >= NE) return;

    int src = __ldg(ei + e);
    int dst = __ldg(ei + NE + e);

    const __half* Ep = d_E + (ull)e * 128 + 2 * lane;
    __half2 hf = __ldcs((const __half2*)Ep);
    __half2 hs = __ldcs((const __half2*)(Ep + 64));
    float2 ef = __half22float2(hf);
    float2 es = __half22float2(hs);

    float2 af  = *(const float2*)(d_Af + dst * HID + 2 * lane);
    float2 bfv = *(const float2*)(d_Bf + src * HID + 2 * lane);
    float2 as  = *(const float2*)(d_As + dst * HID + 2 * lane);
    float2 bsv = *(const float2*)(d_Bs + src * HID + 2 * lane);

    float pf0 = ef.x + af.x + bfv.x;
    float pf1 = ef.y + af.y + bfv.y;
    float ps0 = es.x + as.x + bsv.x;
    float ps1 = es.y + as.y + bsv.y;

    float m0 = sigmoidf_(pf0) * softplusf_(ps0);
    float m1 = sigmoidf_(pf1) * softplusf_(ps1);

    float* dp = d_agg + dst * HID + 2 * lane;
    asm volatile("red.global.add.v2.f32 [%0], {%1,%2};"
                 :: "l"(dp), "f"(m0), "f"(m1) : "memory");
}

// channel-wise sum / sumsq of d_agg (fp32 inner partials, double block reduce)
__global__ void k_stats_agg() {
    int tid = threadIdx.x;
    int c = tid & 63;
    float s = 0.f, q = 0.f;
    int stride = gridDim.x * blockDim.x;
    for (int i = blockIdx.x * blockDim.x + tid; i < NN * HID; i += stride) {
        float v = d_agg[i];
        s += v; q = fmaf(v, v, q);
    }
    __shared__ float ss[256], sq[256];
    ss[tid] = s; sq[tid] = q;
    __syncthreads();
    if (tid < 64) {
        double S = (double)ss[tid] + (double)ss[tid + 64] + (double)ss[tid + 128] + (double)ss[tid + 192];
        double Q = (double)sq[tid] + (double)sq[tid + 64] + (double)sq[tid + 128] + (double)sq[tid + 192];
        atomicAdd(&d_sum1[c], S);
        atomicAdd(&d_sumsq1[c], Q);
    }
}

// apply cbn + residual, write x_new into d_agg, accumulate obn stats
__global__ void k_apply_cbn(const float* __restrict__ gc, const float* __restrict__ bc) {
    int tid = threadIdx.x;
    int c = tid & 63;
    double mean = d_sum1[c] * (1.0 / NN);
    double var  = d_sumsq1[c] * (1.0 / NN) - mean * mean;
    float rs = (float)rsqrt(var + 1e-5);
    float mn = (float)mean;
    float g = gc[c], b = bc[c];

    float s = 0.f, q = 0.f;
    int stride = gridDim.x * blockDim.x;
    for (int i = blockIdx.x * blockDim.x + tid; i < NN * HID; i += stride) {
        float xn = (d_agg[i] - mn) * rs * g + b + d_x[i];
        d_agg[i] = xn;
        s += xn; q = fmaf(xn, xn, q);
    }
    __shared__ float ss[256], sq[256];
    ss[tid] = s; sq[tid] = q;
    __syncthreads();
    if (tid < 64) {
        double S = (double)ss[tid] + (double)ss[tid + 64] + (double)ss[tid + 128] + (double)ss[tid + 192];
        double Q = (double)sq[tid] + (double)sq[tid + 64] + (double)sq[tid + 128] + (double)sq[tid + 192];
        atomicAdd(&d_sum2[c], S);
        atomicAdd(&d_sumsq2[c], Q);
    }
}

// apply obn + softplus -> d_x
__global__ void k_apply_obn(const float* __restrict__ go, const float* __restrict__ bo) {
    int i = blockIdx.x * blockDim.x + threadIdx.x;
    if (i >= NN * HID) return;
    int c = i & 63;
    double mean = d_sum2[c] * (1.0 / NN);
    double var  = d_sumsq2[c] * (1.0 / NN) - mean * mean;
    float rs = (float)rsqrt(var + 1e-5);
    float xv = (d_agg[i] - (float)mean) * rs * go[c] + bo[c];
    d_x[i] = softplusf_(xv);
}

__global__ void k_pool(const int* __restrict__ batch) {
    int i = blockIdx.x * blockDim.x + threadIdx.x;
    if (i < NN * 16) {
        int n = i >> 4, q = i & 15;
        int g = batch[n];
        float4 v = *(const float4*)(d_x + n * HID + 4 * q);
        float* p = d_pool + g * HID + 4 * q;
        asm volatile("red.global.add.v4.f32 [%0], {%1,%2,%3,%4};"
                     :: "l"(p), "f"(v.x), "f"(v.y), "f"(v.z), "f"(v.w) : "memory");
    }
}

__global__ void k_cnt(const int* __restrict__ batch) {
    int n = blockIdx.x * blockDim.x + threadIdx.x;
    if (n < NN) atomicAdd(&d_cnt[batch[n]], 1.0f);
}

__global__ void k_head(const float* __restrict__ W1, const float* __restrict__ b1,
                       const float* __restrict__ W2, const float* __restrict__ b2,
                       float* __restrict__ out)
{
    int g = blockIdx.x;
    int t = threadIdx.x;
    __shared__ float sp[64];
    __shared__ float sh[64];
    float cnt = fmaxf(d_cnt[g], 1.0f);
    sp[t] = d_pool[g * HID + t] / cnt;
    __syncthreads();
    float acc = b1[t];
#pragma unroll
    for (int k = 0; k < 64; k++)
        acc = fmaf(sp[k], W1[k * HID + t], acc);
    float h = acc * sigmoidf_(acc);
    sh[t] = h * W2[t];
    __syncthreads();
    if (t < 32) {
        float v = sh[t] + sh[t + 32];
#pragma unroll
        for (int o = 16; o > 0; o >>= 1)
            v += __shfl_down_sync(0xffffffffu, v, o);
        if (t == 0) out[g] = v + b2[0];
    }
}

// ---------------- launch ----------------
extern "C" void kernel_launch(void* const* d_in, const int* in_sizes, int n_in,
                              void* d_out, int out_size) {
    const int*   z     = (const int*)  d_in[0];
    const int*   ei    = (const int*)  d_in[1];
    const float* ea    = (const float*)d_in[2];
    const int*   batch = (const int*)  d_in[3];
    const float* emb   = (const float*)d_in[4];
    const float* Wf    = (const float*)d_in[5];
    const float* bf    = (const float*)d_in[6];
    const float* Ws    = (const float*)d_in[7];
    const float* bs    = (const float*)d_in[8];
    const float* gc    = (const float*)d_in[9];
    const float* bc    = (const float*)d_in[10];
    const float* go    = (const float*)d_in[11];
    const float* bo    = (const float*)d_in[12];
    const float* W1    = (const float*)d_in[13];
    const float* b1    = (const float*)d_in[14];
    const float* W2    = (const float*)d_in[15];
    const float* b2    = (const float*)d_in[16];
    float* out = (float*)d_out;

    k_gather<<<(NN * HID + 255) / 256, 256>>>(z, emb);

    for (int l = 0; l < NLAYERS; l++) {
        const float* Wfl = Wf + l * ZW * HID;
        const float* Wsl = Ws + l * ZW * HID;
        k_node_pre<<<(NN + 63) / 64, 128>>>(Wfl, bf + l * HID, Wsl, bs + l * HID);
        k_zero_layer<<<(NN * HID + 255) / 256, 256>>>();
        k_edge_gemm<<<740, 128>>>(ea, Wfl, Wsl);
        k_edge_apply<<<(NE * 32 + 255) / 256, 256>>>(ei);
        k_stats_agg<<<256, 256>>>();
        k_apply_cbn<<<256, 256>>>(gc + l * HID, bc + l * HID);
        k_apply_obn<<<(NN * HID + 255) / 256, 256>>>(go + l * HID, bo + l * HID);
    }

    k_zero_pool<<<(NG * HID + 255) / 256, 256>>>();
    k_pool<<<(NN * 16 + 255) / 256, 256>>>(batch);
    k_cnt<<<(NN + 255) / 256, 256>>>(batch);
    k_head<<<NG, 64>>>(W1, b1, W2, b2, out);
}

// round 3
// speedup vs baseline: 1.6031x; 1.0993x over previous
#include <cuda_runtime.h>
#include <cuda_fp16.h>

#define NN 100000
#define NE 1000000
#define NG 512
#define HID 64
#define EDIM 32
#define ZW 160
#define NLAYERS 4

typedef unsigned long long ull;
typedef unsigned int uint;

// ---------------- scratch (static device globals; no allocation) ----------------
__device__ float d_x[NN * HID];       // node features (fp32)
__device__ uint  d_nd[NN * 64];       // dst terms: [n*64+2l]=half2(Af), [n*64+2l+1]=half2(As)  (bias included)
__device__ uint  d_ns[NN * 64];       // src terms: half2(Bf), half2(Bs)
__device__ float d_agg[NN * HID];     // edge aggregation, then x_new in-place
__device__ double d_sum1[HID];
__device__ double d_sumsq1[HID];
__device__ double d_sum2[HID];
__device__ double d_sumsq2[HID];
__device__ float d_pool[NG * HID];
__device__ float d_cnt[NG];

// ---------------- packed f32x2 helpers (Blackwell) ----------------
__device__ __forceinline__ ull pk2(float a, float b) {
    ull r; asm("mov.b64 %0,{%1,%2};" : "=l"(r) : "f"(a), "f"(b)); return r;
}
__device__ __forceinline__ void upk2(ull v, float& a, float& b) {
    asm("mov.b64 {%0,%1},%2;" : "=f"(a), "=f"(b) : "l"(v));
}
__device__ __forceinline__ ull ffma2(ull a, ull b, ull c) {
    ull d; asm("fma.rn.f32x2 %0,%1,%2,%3;" : "=l"(d) : "l"(a), "l"(b), "l"(c)); return d;
}

__device__ __forceinline__ float sigmoidf_(float x) {
    return __fdividef(1.0f, 1.0f + __expf(-x));
}
__device__ __forceinline__ float softplusf_(float x) {
    float e = __expf(-fabsf(x));
    return fmaxf(x, 0.0f) + __logf(1.0f + e);
}

// ---------------- kernels ----------------

// gather embeddings AND zero d_agg for layer 0
__global__ void k_gather(const int* __restrict__ z, const float* __restrict__ emb) {
    int i = blockIdx.x * blockDim.x + threadIdx.x;
    if (i < NN * HID) {
        int n = i >> 6, c = i & 63;
        d_x[i] = emb[z[n] * HID + c];
        d_agg[i] = 0.f;
    }
}

// Per-node pre-GEMM: warp0->Af(+bf), warp1->Bf, warp2->As(+bs), warp3->Bs.
// Output packed fp16 into interleaved d_nd/d_ns. Block 0 also zeros BN sums.
__global__ __launch_bounds__(128) void k_node_pre(
    const float* __restrict__ Wf, const float* __restrict__ bf,
    const float* __restrict__ Ws, const float* __restrict__ bs)
{
    __shared__ float sx[64][HID];
    int warp = threadIdx.x >> 5;
    int lane = threadIdx.x & 31;

    if (blockIdx.x == 0 && threadIdx.x < 64) {
        d_sum1[threadIdx.x] = 0.0; d_sumsq1[threadIdx.x] = 0.0;
        d_sum2[threadIdx.x] = 0.0; d_sumsq2[threadIdx.x] = 0.0;
    }

    const float* Wsrc;
    float bias0 = 0.f, bias1 = 0.f;
    uint* outp;
    int slot;
    if (warp == 0)      { Wsrc = Wf;            bias0 = bf[2*lane]; bias1 = bf[2*lane+1]; outp = d_nd; slot = 0; }
    else if (warp == 1) { Wsrc = Wf + 64 * HID;                                            outp = d_ns; slot = 0; }
    else if (warp == 2) { Wsrc = Ws;            bias0 = bs[2*lane]; bias1 = bs[2*lane+1]; outp = d_nd; slot = 1; }
    else                { Wsrc = Ws + 64 * HID;                                            outp = d_ns; slot = 1; }

    ull w[64];
#pragma unroll
    for (int k = 0; k < 64; k++) {
        float2 t = *(const float2*)(Wsrc + k * HID + 2 * lane);
        w[k] = pk2(t.x, t.y);
    }

    int nb = blockIdx.x * 64;
    int nmax = NN - nb; if (nmax > 64) nmax = 64;

    for (int i = threadIdx.x; i < nmax * HID; i += 128)
        sx[i >> 6][i & 63] = d_x[nb * HID + i];
    __syncthreads();

    for (int n = 0; n < nmax; n++) {
        ull a0 = pk2(bias0, bias1), a1 = 0ull, a2 = 0ull, a3 = 0ull;
#pragma unroll
        for (int k = 0; k < 64; k += 4) {
            float x0 = sx[n][k], x1 = sx[n][k+1], x2 = sx[n][k+2], x3 = sx[n][k+3];
            a0 = ffma2(pk2(x0, x0), w[k],   a0);
            a1 = ffma2(pk2(x1, x1), w[k+1], a1);
            a2 = ffma2(pk2(x2, x2), w[k+2], a2);
            a3 = ffma2(pk2(x3, x3), w[k+3], a3);
        }
        float r0a, r0b, r1a, r1b, r2a, r2b, r3a, r3b;
        upk2(a0, r0a, r0b); upk2(a1, r1a, r1b); upk2(a2, r2a, r2b); upk2(a3, r3a, r3b);
        float c0 = (r0a + r1a) + (r2a + r3a);
        float c1 = (r0b + r1b) + (r2b + r3b);
        __half2 h = __floats2half2_rn(c0, c1);
        outp[(ull)(nb + n) * 64 + 2 * lane + slot] = *(uint*)&h;
    }
}

__global__ void k_zero_pool() {
    int i = blockIdx.x * blockDim.x + threadIdx.x;
    if (i < NG * HID) d_pool[i] = 0.f;
    if (i < NG) d_cnt[i] = 0.f;
}

// Fused edge kernel: GEMM a 32-edge tile into smem, then gather+activate+scatter.
// warp&1 selects f/s matrix half for the GEMM phase (weights in 32 ull regs/lane).
__global__ __launch_bounds__(128) void k_edge_fused(
    const int* __restrict__ ei, const float* __restrict__ ea,
    const float* __restrict__ Wf, const float* __restrict__ Ws)
{
    __shared__ float sea[32][EDIM];   // edge_attr tile
    __shared__ float sE[32][128];     // GEMM result: [e][0:64]=f, [64:128]=s
    __shared__ int ssrc[32], sdst[32];

    int warp = threadIdx.x >> 5;
    int lane = threadIdx.x & 31;
    const float* W = (warp & 1) ? Ws : Wf;

    ull w[32];
#pragma unroll
    for (int k = 0; k < 32; k++) {
        float2 t = *(const float2*)(W + (128 + k) * HID + 2 * lane);
        w[k] = pk2(t.x, t.y);
    }

    int eoff = (warp >> 1) * 16;
    int outc = (warp & 1) * 64 + 2 * lane;

    for (int base = blockIdx.x * 32; base < NE; base += gridDim.x * 32) {
        // load indices + ea tile
        if (threadIdx.x < 32)       ssrc[threadIdx.x]      = ei[base + threadIdx.x];
        else if (threadIdx.x < 64)  sdst[threadIdx.x - 32] = ei[NE + base + threadIdx.x - 32];
        const float4* s4 = (const float4*)(ea + (ull)base * EDIM);
        float4* t4 = (float4*)&sea[0][0];
#pragma unroll
        for (int i = threadIdx.x; i < 256; i += 128)
            t4[i] = __ldcs(s4 + i);
        __syncthreads();

        // ---- GEMM phase: 16 edges per warp, 2 cols per lane ----
#pragma unroll 2
        for (int t = 0; t < 16; t++) {
            int e = eoff + t;
            ull a0 = 0ull, a1 = 0ull, a2 = 0ull, a3 = 0ull;
#pragma unroll
            for (int k = 0; k < 32; k += 4) {
                float4 v = *(const float4*)&sea[e][k];
                a0 = ffma2(pk2(v.x, v.x), w[k],   a0);
                a1 = ffma2(pk2(v.y, v.y), w[k+1], a1);
                a2 = ffma2(pk2(v.z, v.z), w[k+2], a2);
                a3 = ffma2(pk2(v.w, v.w), w[k+3], a3);
            }
            float r0a, r0b, r1a, r1b, r2a, r2b, r3a, r3b;
            upk2(a0, r0a, r0b); upk2(a1, r1a, r1b);
            upk2(a2, r2a, r2b); upk2(a3, r3a, r3b);
            float2 r;
            r.x = (r0a + r1a) + (r2a + r3a);
            r.y = (r0b + r1b) + (r2b + r3b);
            *(float2*)&sE[e][outc] = r;
        }
        __syncthreads();

        // ---- apply phase: 8 edges per warp ----
#pragma unroll
        for (int t = 0; t < 8; t++) {
            int e = warp * 8 + t;
            int src = ssrc[e];
            int dst = sdst[e];

            uint2 nd = *(const uint2*)&d_nd[(ull)dst * 64 + 2 * lane];
            uint2 ns = *(const uint2*)&d_ns[(ull)src * 64 + 2 * lane];
            float2 afv = __half22float2(*(__half2*)&nd.x);
            float2 asv = __half22float2(*(__half2*)&nd.y);
            float2 bfv = __half22float2(*(__half2*)&ns.x);
            float2 bsv = __half22float2(*(__half2*)&ns.y);

            float2 Ef = *(const float2*)&sE[e][2 * lane];
            float2 Es = *(const float2*)&sE[e][64 + 2 * lane];

            float pf0 = Ef.x + afv.x + bfv.x;
            float pf1 = Ef.y + afv.y + bfv.y;
            float ps0 = Es.x + asv.x + bsv.x;
            float ps1 = Es.y + asv.y + bsv.y;

            float m0 = sigmoidf_(pf0) * softplusf_(ps0);
            float m1 = sigmoidf_(pf1) * softplusf_(ps1);

            float* dp = d_agg + (ull)dst * HID + 2 * lane;
            asm volatile("red.global.add.v2.f32 [%0], {%1,%2};"
                         :: "l"(dp), "f"(m0), "f"(m1) : "memory");
        }
        __syncthreads();
    }
}

// channel-wise sum / sumsq of d_agg (fp32 inner partials, double block reduce)
__global__ void k_stats_agg() {
    int tid = threadIdx.x;
    int c = tid & 63;
    float s = 0.f, q = 0.f;
    int stride = gridDim.x * blockDim.x;
    for (int i = blockIdx.x * blockDim.x + tid; i < NN * HID; i += stride) {
        float v = d_agg[i];
        s += v; q = fmaf(v, v, q);
    }
    __shared__ float ss[256], sq[256];
    ss[tid] = s; sq[tid] = q;
    __syncthreads();
    if (tid < 64) {
        double S = (double)ss[tid] + (double)ss[tid + 64] + (double)ss[tid + 128] + (double)ss[tid + 192];
        double Q = (double)sq[tid] + (double)sq[tid + 64] + (double)sq[tid + 128] + (double)sq[tid + 192];
        atomicAdd(&d_sum1[c], S);
        atomicAdd(&d_sumsq1[c], Q);
    }
}

// apply cbn + residual, write x_new into d_agg, accumulate obn stats
__global__ void k_apply_cbn(const float* __restrict__ gc, const float* __restrict__ bc) {
    int tid = threadIdx.x;
    int c = tid & 63;
    double mean = d_sum1[c] * (1.0 / NN);
    double var  = d_sumsq1[c] * (1.0 / NN) - mean * mean;
    float rs = (float)rsqrt(var + 1e-5);
    float mn = (float)mean;
    float g = gc[c], b = bc[c];

    float s = 0.f, q = 0.f;
    int stride = gridDim.x * blockDim.x;
    for (int i = blockIdx.x * blockDim.x + tid; i < NN * HID; i += stride) {
        float xn = (d_agg[i] - mn) * rs * g + b + d_x[i];
        d_agg[i] = xn;
        s += xn; q = fmaf(xn, xn, q);
    }
    __shared__ float ss[256], sq[256];
    ss[tid] = s; sq[tid] = q;
    __syncthreads();
    if (tid < 64) {
        double S = (double)ss[tid] + (double)ss[tid + 64] + (double)ss[tid + 128] + (double)ss[tid + 192];
        double Q = (double)sq[tid] + (double)sq[tid + 64] + (double)sq[tid + 128] + (double)sq[tid + 192];
        atomicAdd(&d_sum2[c], S);
        atomicAdd(&d_sumsq2[c], Q);
    }
}

// apply obn + softplus -> d_x; also zero d_agg for next layer
__global__ void k_apply_obn(const float* __restrict__ go, const float* __restrict__ bo) {
    int i = blockIdx.x * blockDim.x + threadIdx.x;
    if (i >= NN * HID) return;
    int c = i & 63;
    double mean = d_sum2[c] * (1.0 / NN);
    double var  = d_sumsq2[c] * (1.0 / NN) - mean * mean;
    float rs = (float)rsqrt(var + 1e-5);
    float xv = (d_agg[i] - (float)mean) * rs * go[c] + bo[c];
    d_x[i] = softplusf_(xv);
    d_agg[i] = 0.f;
}

__global__ void k_pool(const int* __restrict__ batch) {
    int i = blockIdx.x * blockDim.x + threadIdx.x;
    if (i < NN * 16) {
        int n = i >> 4, q = i & 15;
        int g = batch[n];
        float4 v = *(const float4*)(d_x + n * HID + 4 * q);
        float* p = d_pool + g * HID + 4 * q;
        asm volatile("red.global.add.v4.f32 [%0], {%1,%2,%3,%4};"
                     :: "l"(p), "f"(v.x), "f"(v.y), "f"(v.z), "f"(v.w) : "memory");
    }
}

__global__ void k_cnt(const int* __restrict__ batch) {
    int n = blockIdx.x * blockDim.x + threadIdx.x;
    if (n < NN) atomicAdd(&d_cnt[batch[n]], 1.0f);
}

__global__ void k_head(const float* __restrict__ W1, const float* __restrict__ b1,
                       const float* __restrict__ W2, const float* __restrict__ b2,
                       float* __restrict__ out)
{
    int g = blockIdx.x;
    int t = threadIdx.x;
    __shared__ float sp[64];
    __shared__ float sh[64];
    float cnt = fmaxf(d_cnt[g], 1.0f);
    sp[t] = d_pool[g * HID + t] / cnt;
    __syncthreads();
    float acc = b1[t];
#pragma unroll
    for (int k = 0; k < 64; k++)
        acc = fmaf(sp[k], W1[k * HID + t], acc);
    float h = acc * sigmoidf_(acc);
    sh[t] = h * W2[t];
    __syncthreads();
    if (t < 32) {
        float v = sh[t] + sh[t + 32];
#pragma unroll
        for (int o = 16; o > 0; o >>= 1)
            v += __shfl_down_sync(0xffffffffu, v, o);
        if (t == 0) out[g] = v + b2[0];
    }
}

// ---------------- launch ----------------
extern "C" void kernel_launch(void* const* d_in, const int* in_sizes, int n_in,
                              void* d_out, int out_size) {
    const int*   z     = (const int*)  d_in[0];
    const int*   ei    = (const int*)  d_in[1];
    const float* ea    = (const float*)d_in[2];
    const int*   batch = (const int*)  d_in[3];
    const float* emb   = (const float*)d_in[4];
    const float* Wf    = (const float*)d_in[5];
    const float* bf    = (const float*)d_in[6];
    const float* Ws    = (const float*)d_in[7];
    const float* bs    = (const float*)d_in[8];
    const float* gc    = (const float*)d_in[9];
    const float* bc    = (const float*)d_in[10];
    const float* go    = (const float*)d_in[11];
    const float* bo    = (const float*)d_in[12];
    const float* W1    = (const float*)d_in[13];
    const float* b1    = (const float*)d_in[14];
    const float* W2    = (const float*)d_in[15];
    const float* b2    = (const float*)d_in[16];
    float* out = (float*)d_out;

    k_gather<<<(NN * HID + 255) / 256, 256>>>(z, emb);

    for (int l = 0; l < NLAYERS; l++) {
        const float* Wfl = Wf + l * ZW * HID;
        const float* Wsl = Ws + l * ZW * HID;
        k_node_pre<<<(NN + 63) / 64, 128>>>(Wfl, bf + l * HID, Wsl, bs + l * HID);
        k_edge_fused<<<740, 128>>>(ei, ea, Wfl, Wsl);
        k_stats_agg<<<256, 256>>>();
        k_apply_cbn<<<256, 256>>>(gc + l * HID, bc + l * HID);
        k_apply_obn<<<(NN * HID + 255) / 256, 256>>>(go + l * HID, bo + l * HID);
    }

    k_zero_pool<<<(NG * HID + 255) / 256, 256>>>();
    k_pool<<<(NN * 16 + 255) / 256, 256>>>(batch);
    k_cnt<<<(NN + 255) / 256, 256>>>(batch);
    k_head<<<NG, 64>>>(W1, b1, W2, b2, out);
}

// round 4
// speedup vs baseline: 2.2734x; 1.4181x over previous
#include <cuda_runtime.h>
#include <cuda_fp16.h>

#define NN 100000
#define NE 1000000
#define NG 512
#define HID 64
#define EDIM 32
#define ZW 160
#define NLAYERS 4

typedef unsigned long long ull;
typedef unsigned int uint;

// ---------------- scratch (static device globals; no allocation) ----------------
__device__ float d_x[NN * HID];       // node features (fp32)
__device__ uint  d_nd[NN * 64];       // dst terms: [n*64+2l]=half2(Af), [+1]=half2(As) (bias incl.)
__device__ uint  d_ns[NN * 64];       // src terms: half2(Bf), half2(Bs)
__device__ float d_agg[NN * HID];     // edge aggregation / x_new
__device__ double d_sum1[NLAYERS][64];   // cbn sums (per layer)
__device__ double d_sumsq1[NLAYERS][64];
__device__ double d_sum2[NLAYERS][64];   // obn sums (per layer)
__device__ double d_sumsq2[NLAYERS][64];
__device__ float d_pool[NG * HID];
__device__ float d_cnt[NG];

// ---------------- packed f32x2 helpers (Blackwell) ----------------
__device__ __forceinline__ ull pk2(float a, float b) {
    ull r; asm("mov.b64 %0,{%1,%2};" : "=l"(r) : "f"(a), "f"(b)); return r;
}
__device__ __forceinline__ void upk2(ull v, float& a, float& b) {
    asm("mov.b64 {%0,%1},%2;" : "=f"(a), "=f"(b) : "l"(v));
}
__device__ __forceinline__ ull ffma2(ull a, ull b, ull c) {
    ull d; asm("fma.rn.f32x2 %0,%1,%2,%3;" : "=l"(d) : "l"(a), "l"(b), "l"(c)); return d;
}

__device__ __forceinline__ float sigmoidf_(float x) {
    return __fdividef(1.0f, 1.0f + __expf(-x));
}
__device__ __forceinline__ float softplusf_(float x) {
    float e = __expf(-fabsf(x));
    return fmaxf(x, 0.0f) + __logf(1.0f + e);
}

// ---------------- kernels ----------------

// gather embeddings, zero d_agg, zero all per-layer BN sums
__global__ void k_gather(const int* __restrict__ z, const float* __restrict__ emb) {
    int i = blockIdx.x * blockDim.x + threadIdx.x;
    if (i < NN * HID) {
        int n = i >> 6, c = i & 63;
        d_x[i] = emb[z[n] * HID + c];
        d_agg[i] = 0.f;
    }
    if (i < NLAYERS * 64) {
        int l = i >> 6, c = i & 63;
        d_sum1[l][c] = 0.0; d_sumsq1[l][c] = 0.0;
        d_sum2[l][c] = 0.0; d_sumsq2[l][c] = 0.0;
    }
}

// Per-node pre-GEMM. If prev_layer >= 0, first applies obn(prev)+softplus to d_agg,
// writing d_x and zeroing d_agg (fuses k_apply_obn of the previous layer).
__global__ __launch_bounds__(128) void k_node_pre(
    const float* __restrict__ Wf, const float* __restrict__ bf,
    const float* __restrict__ Ws, const float* __restrict__ bs,
    const float* __restrict__ go, const float* __restrict__ bo,
    int prev_layer)
{
    __shared__ float sx[64][HID];
    int warp = threadIdx.x >> 5;
    int lane = threadIdx.x & 31;
    int tid = threadIdx.x;

    float mn = 0.f, rsg = 0.f, bb = 0.f;   // obn params for channel tid&63
    if (prev_layer >= 0) {
        int c = tid & 63;
        double mean = d_sum2[prev_layer][c] * (1.0 / NN);
        double var  = d_sumsq2[prev_layer][c] * (1.0 / NN) - mean * mean;
        float rs = (float)rsqrt(var + 1e-5);
        mn = (float)mean;
        rsg = rs * go[c];
        bb = bo[c];
    }

    const float* Wsrc;
    float bias0 = 0.f, bias1 = 0.f;
    uint* outp;
    int slot;
    if (warp == 0)      { Wsrc = Wf;            bias0 = bf[2*lane]; bias1 = bf[2*lane+1]; outp = d_nd; slot = 0; }
    else if (warp == 1) { Wsrc = Wf + 64 * HID;                                            outp = d_ns; slot = 0; }
    else if (warp == 2) { Wsrc = Ws;            bias0 = bs[2*lane]; bias1 = bs[2*lane+1]; outp = d_nd; slot = 1; }
    else                { Wsrc = Ws + 64 * HID;                                            outp = d_ns; slot = 1; }

    ull w[64];
#pragma unroll
    for (int k = 0; k < 64; k++) {
        float2 t = *(const float2*)(Wsrc + k * HID + 2 * lane);
        w[k] = pk2(t.x, t.y);
    }

    int nb = blockIdx.x * 64;
    int nmax = NN - nb; if (nmax > 64) nmax = 64;

    for (int i = tid; i < nmax * HID; i += 128) {
        int gi = nb * HID + i;
        float v;
        if (prev_layer >= 0) {
            float xv = (d_agg[gi] - mn) * rsg + bb;
            v = softplusf_(xv);
            d_x[gi] = v;
            d_agg[gi] = 0.f;
        } else {
            v = d_x[gi];
        }
        sx[i >> 6][i & 63] = v;
    }
    __syncthreads();

    for (int n = 0; n < nmax; n++) {
        ull a0 = pk2(bias0, bias1), a1 = 0ull, a2 = 0ull, a3 = 0ull;
#pragma unroll
        for (int k = 0; k < 64; k += 4) {
            float x0 = sx[n][k], x1 = sx[n][k+1], x2 = sx[n][k+2], x3 = sx[n][k+3];
            a0 = ffma2(pk2(x0, x0), w[k],   a0);
            a1 = ffma2(pk2(x1, x1), w[k+1], a1);
            a2 = ffma2(pk2(x2, x2), w[k+2], a2);
            a3 = ffma2(pk2(x3, x3), w[k+3], a3);
        }
        float r0a, r0b, r1a, r1b, r2a, r2b, r3a, r3b;
        upk2(a0, r0a, r0b); upk2(a1, r1a, r1b); upk2(a2, r2a, r2b); upk2(a3, r3a, r3b);
        float c0 = (r0a + r1a) + (r2a + r3a);
        float c1 = (r0b + r1b) + (r2b + r3b);
        __half2 h = __floats2half2_rn(c0, c1);
        outp[(ull)(nb + n) * 64 + 2 * lane + slot] = *(uint*)&h;
    }
}

__global__ void k_zero_pool() {
    int i = blockIdx.x * blockDim.x + threadIdx.x;
    if (i < NG * HID) d_pool[i] = 0.f;
    if (i < NG) d_cnt[i] = 0.f;
}

// Fused edge kernel with software pipelining + gather prefetch.
__global__ __launch_bounds__(128) void k_edge_fused(
    const int* __restrict__ ei, const float* __restrict__ ea,
    const float* __restrict__ Wf, const float* __restrict__ Ws)
{
    __shared__ float sea[32][EDIM];   // edge_attr tile (current)
    __shared__ float sE[32][128];     // GEMM result
    __shared__ int sidx[64];          // [0:32)=src, [32:64)=dst

    int tid = threadIdx.x;
    int warp = tid >> 5;
    int lane = tid & 31;
    const float* W = (warp & 1) ? Ws : Wf;

    ull w[32];
#pragma unroll
    for (int k = 0; k < 32; k++) {
        float2 t = *(const float2*)(W + (128 + k) * HID + 2 * lane);
        w[k] = pk2(t.x, t.y);
    }

    int eoff = (warp >> 1) * 16;
    int outc = (warp & 1) * 64 + 2 * lane;
    const int stride = gridDim.x * 32;

    int base = blockIdx.x * 32;

    // prologue: load tile 'base'
    if (base < NE) {
        if (tid < 32)      sidx[tid]      = ei[base + tid];
        else if (tid < 64) sidx[tid]      = ei[NE + base + tid - 32];
        const float4* s4 = (const float4*)(ea + (ull)base * EDIM);
        float4* t4 = (float4*)&sea[0][0];
        t4[tid]       = __ldcs(s4 + tid);
        t4[tid + 128] = __ldcs(s4 + tid + 128);
    }
    __syncthreads();

    for (; base < NE; base += stride) {
        int nb = base + stride;
        int lb = (nb < NE) ? nb : 0;   // clamped prefetch base (last iter loads dummies)

        // this tile's indices for this warp's apply set
        int srcs[8], dsts[8];
#pragma unroll
        for (int t = 0; t < 8; t++) {
            srcs[t] = sidx[warp * 8 + t];
            dsts[t] = sidx[32 + warp * 8 + t];
        }

        // issue next-tile loads into registers (overlap with GEMM)
        const float4* s4 = (const float4*)(ea + (ull)lb * EDIM);
        float4 n0 = __ldcs(s4 + tid);
        float4 n1 = __ldcs(s4 + tid + 128);
        int nidx = 0;
        if (tid < 32)      nidx = ei[lb + tid];
        else if (tid < 64) nidx = ei[NE + lb + tid - 32];

        // ---- GEMM phase: 16 edges per warp, 2 cols per lane ----
#pragma unroll 2
        for (int t = 0; t < 16; t++) {
            int e = eoff + t;
            ull a0 = 0ull, a1 = 0ull, a2 = 0ull, a3 = 0ull;
#pragma unroll
            for (int k = 0; k < 32; k += 4) {
                float4 v = *(const float4*)&sea[e][k];
                a0 = ffma2(pk2(v.x, v.x), w[k],   a0);
                a1 = ffma2(pk2(v.y, v.y), w[k+1], a1);
                a2 = ffma2(pk2(v.z, v.z), w[k+2], a2);
                a3 = ffma2(pk2(v.w, v.w), w[k+3], a3);
            }
            float r0a, r0b, r1a, r1b, r2a, r2b, r3a, r3b;
            upk2(a0, r0a, r0b); upk2(a1, r1a, r1b);
            upk2(a2, r2a, r2b); upk2(a3, r3a, r3b);
            float2 r;
            r.x = (r0a + r1a) + (r2a + r3a);
            r.y = (r0b + r1b) + (r2b + r3b);
            *(float2*)&sE[e][outc] = r;
        }
        __syncthreads();   // sE ready; sea/sidx free

        // store next tile into sea/sidx (safe: all GEMMs done, apply doesn't read them)
        {
            float4* t4 = (float4*)&sea[0][0];
            t4[tid]       = n0;
            t4[tid + 128] = n1;
            if (tid < 64) sidx[tid] = nidx;
        }

        // ---- apply phase: prefetch all 16 gathers, then compute ----
        uint2 nd[8], ns[8];
#pragma unroll
        for (int t = 0; t < 8; t++) {
            nd[t] = *(const uint2*)&d_nd[(ull)dsts[t] * 64 + 2 * lane];
            ns[t] = *(const uint2*)&d_ns[(ull)srcs[t] * 64 + 2 * lane];
        }
#pragma unroll
        for (int t = 0; t < 8; t++) {
            int e = warp * 8 + t;
            float2 afv = __half22float2(*(__half2*)&nd[t].x);
            float2 asv = __half22float2(*(__half2*)&nd[t].y);
            float2 bfv = __half22float2(*(__half2*)&ns[t].x);
            float2 bsv = __half22float2(*(__half2*)&ns[t].y);

            float2 Ef = *(const float2*)&sE[e][2 * lane];
            float2 Es = *(const float2*)&sE[e][64 + 2 * lane];

            float pf0 = Ef.x + afv.x + bfv.x;
            float pf1 = Ef.y + afv.y + bfv.y;
            float ps0 = Es.x + asv.x + bsv.x;
            float ps1 = Es.y + asv.y + bsv.y;

            float m0 = sigmoidf_(pf0) * softplusf_(ps0);
            float m1 = sigmoidf_(pf1) * softplusf_(ps1);

            float* dp = d_agg + (ull)dsts[t] * HID + 2 * lane;
            asm volatile("red.global.add.v2.f32 [%0], {%1,%2};"
                         :: "l"(dp), "f"(m0), "f"(m1) : "memory");
        }
        __syncthreads();   // sE free for next GEMM; sea stores visible
    }
}

// float4-vectorized channel stats of d_agg -> d_sum1[layer]
__global__ void k_stats_agg(int layer) {
    int tid = threadIdx.x;
    int g = tid & 15;                 // channel group: channels 4g..4g+3
    float4 s = {0,0,0,0}, q = {0,0,0,0};
    int stride = gridDim.x * blockDim.x;   // multiple of 16
    const float4* a4 = (const float4*)d_agg;
    for (int i = blockIdx.x * blockDim.x + tid; i < NN * 16; i += stride) {
        float4 v = a4[i];
        s.x += v.x; s.y += v.y; s.z += v.z; s.w += v.w;
        q.x = fmaf(v.x, v.x, q.x); q.y = fmaf(v.y, v.y, q.y);
        q.z = fmaf(v.z, v.z, q.z); q.w = fmaf(v.w, v.w, q.w);
    }
    __shared__ float4 ss[256], sq[256];
    ss[tid] = s; sq[tid] = q;
    __syncthreads();
#pragma unroll
    for (int o = 128; o >= 16; o >>= 1) {
        if (tid < o) {
            ss[tid].x += ss[tid+o].x; ss[tid].y += ss[tid+o].y;
            ss[tid].z += ss[tid+o].z; ss[tid].w += ss[tid+o].w;
            sq[tid].x += sq[tid+o].x; sq[tid].y += sq[tid+o].y;
            sq[tid].z += sq[tid+o].z; sq[tid].w += sq[tid+o].w;
        }
        __syncthreads();
    }
    if (tid < 16) {
        atomicAdd(&d_sum1[layer][4*tid+0], (double)ss[tid].x);
        atomicAdd(&d_sum1[layer][4*tid+1], (double)ss[tid].y);
        atomicAdd(&d_sum1[layer][4*tid+2], (double)ss[tid].z);
        atomicAdd(&d_sum1[layer][4*tid+3], (double)ss[tid].w);
        atomicAdd(&d_sumsq1[layer][4*tid+0], (double)sq[tid].x);
        atomicAdd(&d_sumsq1[layer][4*tid+1], (double)sq[tid].y);
        atomicAdd(&d_sumsq1[layer][4*tid+2], (double)sq[tid].z);
        atomicAdd(&d_sumsq1[layer][4*tid+3], (double)sq[tid].w);
    }
}

// apply cbn + residual (float4), write x_new into d_agg, accumulate obn stats
__global__ void k_apply_cbn(const float* __restrict__ gc, const float* __restrict__ bc, int layer) {
    int tid = threadIdx.x;
    int g = tid & 15;
    float mn[4], rsg[4], bb[4];
#pragma unroll
    for (int j = 0; j < 4; j++) {
        int c = 4 * g + j;
        double mean = d_sum1[layer][c] * (1.0 / NN);
        double var  = d_sumsq1[layer][c] * (1.0 / NN) - mean * mean;
        float rs = (float)rsqrt(var + 1e-5);
        mn[j] = (float)mean; rsg[j] = rs * gc[c]; bb[j] = bc[c];
    }
    float4 s = {0,0,0,0}, q = {0,0,0,0};
    int stride = gridDim.x * blockDim.x;
    float4* a4 = (float4*)d_agg;
    const float4* x4 = (const float4*)d_x;
    for (int i = blockIdx.x * blockDim.x + tid; i < NN * 16; i += stride) {
        float4 a = a4[i];
        float4 x = x4[i];
        float4 xn;
        xn.x = (a.x - mn[0]) * rsg[0] + bb[0] + x.x;
        xn.y = (a.y - mn[1]) * rsg[1] + bb[1] + x.y;
        xn.z = (a.z - mn[2]) * rsg[2] + bb[2] + x.z;
        xn.w = (a.w - mn[3]) * rsg[3] + bb[3] + x.w;
        a4[i] = xn;
        s.x += xn.x; s.y += xn.y; s.z += xn.z; s.w += xn.w;
        q.x = fmaf(xn.x, xn.x, q.x); q.y = fmaf(xn.y, xn.y, q.y);
        q.z = fmaf(xn.z, xn.z, q.z); q.w = fmaf(xn.w, xn.w, q.w);
    }
    __shared__ float4 ss[256], sq[256];
    ss[tid] = s; sq[tid] = q;
    __syncthreads();
#pragma unroll
    for (int o = 128; o >= 16; o >>= 1) {
        if (tid < o) {
            ss[tid].x += ss[tid+o].x; ss[tid].y += ss[tid+o].y;
            ss[tid].z += ss[tid+o].z; ss[tid].w += ss[tid+o].w;
            sq[tid].x += sq[tid+o].x; sq[tid].y += sq[tid+o].y;
            sq[tid].z += sq[tid+o].z; sq[tid].w += sq[tid+o].w;
        }
        __syncthreads();
    }
    if (tid < 16) {
        atomicAdd(&d_sum2[layer][4*tid+0], (double)ss[tid].x);
        atomicAdd(&d_sum2[layer][4*tid+1], (double)ss[tid].y);
        atomicAdd(&d_sum2[layer][4*tid+2], (double)ss[tid].z);
        atomicAdd(&d_sum2[layer][4*tid+3], (double)ss[tid].w);
        atomicAdd(&d_sumsq2[layer][4*tid+0], (double)sq[tid].x);
        atomicAdd(&d_sumsq2[layer][4*tid+1], (double)sq[tid].y);
        atomicAdd(&d_sumsq2[layer][4*tid+2], (double)sq[tid].z);
        atomicAdd(&d_sumsq2[layer][4*tid+3], (double)sq[tid].w);
    }
}

// final obn + softplus -> d_x (last layer only; float4)
__global__ void k_final_obn(const float* __restrict__ go, const float* __restrict__ bo, int layer) {
    int tid = threadIdx.x;
    int g = tid & 15;
    float mn[4], rsg[4], bb[4];
#pragma unroll
    for (int j = 0; j < 4; j++) {
        int c = 4 * g + j;
        double mean = d_sum2[layer][c] * (1.0 / NN);
        double var  = d_sumsq2[layer][c] * (1.0 / NN) - mean * mean;
        float rs = (float)rsqrt(var + 1e-5);
        mn[j] = (float)mean; rsg[j] = rs * go[c]; bb[j] = bo[c];
    }
    int stride = gridDim.x * blockDim.x;
    const float4* a4 = (const float4*)d_agg;
    float4* x4 = (float4*)d_x;
    for (int i = blockIdx.x * blockDim.x + tid; i < NN * 16; i += stride) {
        float4 a = a4[i];
        float4 r;
        r.x = softplusf_((a.x - mn[0]) * rsg[0] + bb[0]);
        r.y = softplusf_((a.y - mn[1]) * rsg[1] + bb[1]);
        r.z = softplusf_((a.z - mn[2]) * rsg[2] + bb[2]);
        r.w = softplusf_((a.w - mn[3]) * rsg[3] + bb[3]);
        x4[i] = r;
    }
}

__global__ void k_pool(const int* __restrict__ batch) {
    int i = blockIdx.x * blockDim.x + threadIdx.x;
    if (i < NN * 16) {
        int n = i >> 4, q = i & 15;
        int g = batch[n];
        float4 v = *(const float4*)(d_x + n * HID + 4 * q);
        float* p = d_pool + g * HID + 4 * q;
        asm volatile("red.global.add.v4.f32 [%0], {%1,%2,%3,%4};"
                     :: "l"(p), "f"(v.x), "f"(v.y), "f"(v.z), "f"(v.w) : "memory");
    }
}

__global__ void k_cnt(const int* __restrict__ batch) {
    int n = blockIdx.x * blockDim.x + threadIdx.x;
    if (n < NN) atomicAdd(&d_cnt[batch[n]], 1.0f);
}

__global__ void k_head(const float* __restrict__ W1, const float* __restrict__ b1,
                       const float* __restrict__ W2, const float* __restrict__ b2,
                       float* __restrict__ out)
{
    int g = blockIdx.x;
    int t = threadIdx.x;
    __shared__ float sp[64];
    __shared__ float sh[64];
    float cnt = fmaxf(d_cnt[g], 1.0f);
    sp[t] = d_pool[g * HID + t] / cnt;
    __syncthreads();
    float acc = b1[t];
#pragma unroll
    for (int k = 0; k < 64; k++)
        acc = fmaf(sp[k], W1[k * HID + t], acc);
    float h = acc * sigmoidf_(acc);
    sh[t] = h * W2[t];
    __syncthreads();
    if (t < 32) {
        float v = sh[t] + sh[t + 32];
#pragma unroll
        for (int o = 16; o > 0; o >>= 1)
            v += __shfl_down_sync(0xffffffffu, v, o);
        if (t == 0) out[g] = v + b2[0];
    }
}

// ---------------- launch ----------------
extern "C" void kernel_launch(void* const* d_in, const int* in_sizes, int n_in,
                              void* d_out, int out_size) {
    const int*   z     = (const int*)  d_in[0];
    const int*   ei    = (const int*)  d_in[1];
    const float* ea    = (const float*)d_in[2];
    const int*   batch = (const int*)  d_in[3];
    const float* emb   = (const float*)d_in[4];
    const float* Wf    = (const float*)d_in[5];
    const float* bf    = (const float*)d_in[6];
    const float* Ws    = (const float*)d_in[7];
    const float* bs    = (const float*)d_in[8];
    const float* gc    = (const float*)d_in[9];
    const float* bc    = (const float*)d_in[10];
    const float* go    = (const float*)d_in[11];
    const float* bo    = (const float*)d_in[12];
    const float* W1    = (const float*)d_in[13];
    const float* b1    = (const float*)d_in[14];
    const float* W2    = (const float*)d_in[15];
    const float* b2    = (const float*)d_in[16];
    float* out = (float*)d_out;

    k_gather<<<(NN * HID + 255) / 256, 256>>>(z, emb);

    for (int l = 0; l < NLAYERS; l++) {
        const float* Wfl = Wf + l * ZW * HID;
        const float* Wsl = Ws + l * ZW * HID;
        // obn of previous layer fused into node_pre (prev_layer = l-1)
        k_node_pre<<<(NN + 63) / 64, 128>>>(Wfl, bf + l * HID, Wsl, bs + l * HID,
                                            go + (l - 1) * HID, bo + (l - 1) * HID, l - 1);
        k_edge_fused<<<740, 128>>>(ei, ea, Wfl, Wsl);
        k_stats_agg<<<256, 256>>>(l);
        k_apply_cbn<<<256, 256>>>(gc + l * HID, bc + l * HID, l);
    }
    k_final_obn<<<256, 256>>>(go + 3 * HID, bo + 3 * HID, 3);

    k_zero_pool<<<(NG * HID + 255) / 256, 256>>>();
    k_pool<<<(NN * 16 + 255) / 256, 256>>>(batch);
    k_cnt<<<(NN + 255) / 256, 256>>>(batch);
    k_head<<<NG, 64>>>(W1, b1, W2, b2, out);
}